// round 2
// baseline (speedup 1.0000x reference)
#include <cuda_runtime.h>
#include <cstdint>

#define B_ 8
#define S_ 256
#define H_ 768
#define K_ 256
#define P_ 50
#define PP 52          // padded P (13 float4)
#define LRS 258        // left/right smem row stride: 258 % 32 == 2 -> conflict-free, 8B-aligned rows

// Scratch for the two projection GEMMs (allocation-free rule: device globals)
__device__ __align__(16) float g_left [B_ * S_ * K_];   // left  = x@u_a + b_s
__device__ __align__(16) float g_right[B_ * S_ * K_];   // right = x@w_a

// ---------------- packed f32x2 helpers (Blackwell FFMA2 path) ----------------
__device__ __forceinline__ unsigned long long pack2(float a, float b) {
    unsigned long long r;
    asm("mov.b64 %0, {%1, %2};" : "=l"(r)
        : "r"(__float_as_uint(a)), "r"(__float_as_uint(b)));
    return r;
}
__device__ __forceinline__ void fma2(unsigned long long& d,
                                     unsigned long long a, unsigned long long b) {
    asm("fma.rn.f32x2 %0, %1, %2, %0;" : "+l"(d) : "l"(a), "l"(b));
}
__device__ __forceinline__ void unpack2(unsigned long long p, float& lo, float& hi) {
    unsigned int l, h;
    asm("mov.b64 {%0, %1}, %2;" : "=r"(l), "=r"(h) : "l"(p));
    lo = __uint_as_float(l);
    hi = __uint_as_float(h);
}

// ---------------- Kernel 1: left/right projections (fused bias) ----------------
// z==0: g_left = x @ u_a + b_s ;  z==1: g_right = x @ w_a
// M = B*S = 2048, N = K = 256, inner = H = 768. 64x64 tile, 16x16 threads, 4x4 micro.
__global__ __launch_bounds__(256) void gemm_lr_kernel(
    const float* __restrict__ x, const float* __restrict__ u_a,
    const float* __restrict__ w_a, const float* __restrict__ b_s)
{
    __shared__ float sX[16][64];   // [kk][row]  (x tile, transposed)
    __shared__ float sW[16][64];   // [kk][col]

    const int z = blockIdx.z;
    const float* __restrict__ w = z ? w_a : u_a;
    float* __restrict__ outp = z ? g_right : g_left;

    const int row0 = blockIdx.y * 64;
    const int col0 = blockIdx.x * 64;
    const int tid = threadIdx.x;
    const int tx = tid & 15, ty = tid >> 4;

    unsigned long long acc[4][2];
#pragma unroll
    for (int i = 0; i < 4; i++) { acc[i][0] = 0ull; acc[i][1] = 0ull; }

    const int lr = tid >> 2;            // 0..63  (x tile row)
    const int lk = (tid & 3) << 2;      // 0,4,8,12
    const int wk = tid >> 4;            // 0..15  (w tile k)
    const int wc = (tid & 15) << 2;     // col offset

    for (int k0 = 0; k0 < H_; k0 += 16) {
        float4 gx = *(const float4*)&x[(row0 + lr) * H_ + k0 + lk];
        float4 gw = *(const float4*)&w[(k0 + wk) * K_ + col0 + wc];
        __syncthreads();
        sX[lk + 0][lr] = gx.x; sX[lk + 1][lr] = gx.y;
        sX[lk + 2][lr] = gx.z; sX[lk + 3][lr] = gx.w;
        *(float4*)&sW[wk][wc] = gw;
        __syncthreads();
#pragma unroll
        for (int kk = 0; kk < 16; kk++) {
            float4 a4 = *(const float4*)&sX[kk][ty * 4];
            float4 b4 = *(const float4*)&sW[kk][tx * 4];
            unsigned long long b01 = pack2(b4.x, b4.y);
            unsigned long long b23 = pack2(b4.z, b4.w);
            unsigned long long a0 = pack2(a4.x, a4.x);
            unsigned long long a1 = pack2(a4.y, a4.y);
            unsigned long long a2 = pack2(a4.z, a4.z);
            unsigned long long a3 = pack2(a4.w, a4.w);
            fma2(acc[0][0], a0, b01); fma2(acc[0][1], a0, b23);
            fma2(acc[1][0], a1, b01); fma2(acc[1][1], a1, b23);
            fma2(acc[2][0], a2, b01); fma2(acc[2][1], a2, b23);
            fma2(acc[3][0], a3, b01); fma2(acc[3][1], a3, b23);
        }
    }

    const int col = col0 + tx * 4;
#pragma unroll
    for (int i = 0; i < 4; i++) {
        float4 o;
        unpack2(acc[i][0], o.x, o.y);
        unpack2(acc[i][1], o.z, o.w);
        if (!z) {
            o.x += b_s[col + 0]; o.y += b_s[col + 1];
            o.z += b_s[col + 2]; o.w += b_s[col + 3];
        }
        *(float4*)&outp[(row0 + ty * 4 + i) * K_ + col] = o;
    }
}

// ---------------- Kernel 2: fused tanh(outer) @ v ----------------
// Block = (16 i) x (16 j) tile of one batch. Thread owns one (i,j) pair and all
// P=50 (padded 52) outputs as 26 packed f32x2 accumulators.
// Per k: t = tanh(l[i][k] + r[j][k]) (bias already folded into left),
//        acc[p-pair] += (t,t) * v[k][p-pair]   (FFMA2)
// KSPLIT=1: single pass, V fully staged (86 KB smem).
// KSPLIT=2: fallback if the 86 KB opt-in is refused — two passes over k,
//           half of V staged at a time (60 KB smem).
template <int KSPLIT>
__global__ __launch_bounds__(256, 2) void fused_tanh_gemm_kernel(
    const float* __restrict__ v, float* __restrict__ out)
{
    constexpr int KC = K_ / KSPLIT;     // k-chunk staged per pass
    extern __shared__ float smem2[];
    float* sL = smem2;                  // 16 * LRS
    float* sR = smem2 + 16 * LRS;       // 16 * LRS
    float* sV = smem2 + 32 * LRS;       // KC * PP

    const int b  = blockIdx.z;
    const int i0 = blockIdx.y * 16;
    const int j0 = blockIdx.x * 16;
    const int tid = threadIdx.x;

    // stage 16 left rows and 16 right rows (each row = K_ floats, coalesced)
    const float* gl = g_left  + (b * S_ + i0) * K_;
    const float* gr = g_right + (b * S_ + j0) * K_;
#pragma unroll
    for (int r = 0; r < 16; r++) {
        sL[r * LRS + tid] = gl[r * K_ + tid];
        sR[r * LRS + tid] = gr[r * K_ + tid];
    }

    const int ti = tid >> 4;
    const int tj = tid & 15;
    const float* myL = sL + ti * LRS;
    const float* myR = sR + tj * LRS;

    unsigned long long acc[26];
#pragma unroll
    for (int q = 0; q < 26; q++) acc[q] = 0ull;

    for (int kc = 0; kc < KSPLIT; kc++) {
        const int kbase = kc * KC;
        if (kc > 0) __syncthreads();   // protect sV reuse across passes
        // stage v chunk (zero-pad cols 50,51 so padded accumulators stay finite)
        for (int idx = tid; idx < KC * PP; idx += 256) {
            int k = idx / PP;
            int p = idx - k * PP;
            sV[idx] = (p < P_) ? v[(kbase + k) * P_ + p] : 0.0f;
        }
        __syncthreads();

#pragma unroll 2
        for (int k2 = 0; k2 < KC; k2 += 2) {
            const int k = kbase + k2;
            // 8B-aligned conflict-free float2 loads (LRS even, stride 2 banks)
            float2 l2 = *(const float2*)&myL[k];
            float2 r2 = *(const float2*)&myR[k];
#pragma unroll
            for (int s = 0; s < 2; s++) {
                float a = (s ? l2.y : l2.x) + (s ? r2.y : r2.x);
                // accurate tanh: 1 - 2/(e^{2a}+1)
                float e = __expf(a + a);
                float t = 1.0f - __fdividef(2.0f, e + 1.0f);
                unsigned long long t2 = pack2(t, t);
                const ulonglong2* vp =
                    (const ulonglong2*)(sV + (k2 + s) * PP);  // broadcast LDS.128
#pragma unroll
                for (int q = 0; q < 13; q++) {
                    ulonglong2 vv = vp[q];
                    fma2(acc[2 * q + 0], t2, vv.x);
                    fma2(acc[2 * q + 1], t2, vv.y);
                }
            }
        }
    }

    float* orow = out + ((size_t)((b * S_ + i0 + ti) * S_) + j0 + tj) * P_;
#pragma unroll
    for (int q = 0; q < 25; q++) {   // 50 floats as 25 float2 stores (8B aligned)
        float lo, hi;
        unpack2(acc[q], lo, hi);
        *(float2*)&orow[2 * q] = make_float2(lo, hi);
    }
}

static const int SMEM_FULL = (32 * LRS + K_ * PP) * (int)sizeof(float);        // 86272
static const int SMEM_HALF = (32 * LRS + (K_ / 2) * PP) * (int)sizeof(float);  // 59648

extern "C" void kernel_launch(void* const* d_in, const int* in_sizes, int n_in,
                              void* d_out, int out_size) {
    const float* x   = (const float*)d_in[0];
    const float* u_a = (const float*)d_in[1];
    const float* w_a = (const float*)d_in[2];
    const float* b_s = (const float*)d_in[3];
    const float* v   = (const float*)d_in[4];
    float* out = (float*)d_out;

    dim3 g1(K_ / 64, (B_ * S_) / 64, 2);      // (4, 32, 2)
    gemm_lr_kernel<<<g1, 256>>>(x, u_a, w_a, b_s);

    dim3 g2(S_ / 16, S_ / 16, B_);            // (16, 16, 8)

    // Opt in to >48 KB dynamic smem. Not a stream op; safe under graph capture.
    cudaError_t e1 = cudaFuncSetAttribute(
        fused_tanh_gemm_kernel<1>,
        cudaFuncAttributeMaxDynamicSharedMemorySize, SMEM_FULL);
    if (e1 == cudaSuccess) {
        fused_tanh_gemm_kernel<1><<<g2, 256, SMEM_FULL>>>(v, out);
    } else {
        cudaFuncSetAttribute(fused_tanh_gemm_kernel<2>,
                             cudaFuncAttributeMaxDynamicSharedMemorySize, SMEM_HALF);
        fused_tanh_gemm_kernel<2><<<g2, 256, SMEM_HALF>>>(v, out);
    }
}

// round 5
// speedup vs baseline: 1.0114x; 1.0114x over previous
#include <cuda_runtime.h>
#include <cstdint>

#define B_ 8
#define S_ 256
#define H_ 768
#define K_ 256
#define P_ 50
#define PP 52          // padded P (13 float4)
#define LRS 258        // smem row stride: even (8B-aligned rows), 258 % 32 == 2 -> conflict-free

// Scratch for the two projection GEMMs (allocation-free rule: device globals)
__device__ __align__(16) float g_left [B_ * S_ * K_];   // left  = x@u_a + b_s
__device__ __align__(16) float g_right[B_ * S_ * K_];   // right = x@w_a

// ---------------- packed f32x2 helpers (Blackwell FFMA2 path) ----------------
__device__ __forceinline__ unsigned long long pack2(float a, float b) {
    unsigned long long r;
    asm("mov.b64 %0, {%1, %2};" : "=l"(r)
        : "r"(__float_as_uint(a)), "r"(__float_as_uint(b)));
    return r;
}
__device__ __forceinline__ void fma2(unsigned long long& d,
                                     unsigned long long a, unsigned long long b) {
    asm("fma.rn.f32x2 %0, %1, %2, %0;" : "+l"(d) : "l"(a), "l"(b));
}
__device__ __forceinline__ void unpack2(unsigned long long p, float& lo, float& hi) {
    unsigned int l, h;
    asm("mov.b64 {%0, %1}, %2;" : "=r"(l), "=r"(h) : "l"(p));
    lo = __uint_as_float(l);
    hi = __uint_as_float(h);
}

// ---------------- Kernel 1: left/right projections (fused bias) ----------------
__global__ __launch_bounds__(256) void gemm_lr_kernel(
    const float* __restrict__ x, const float* __restrict__ u_a,
    const float* __restrict__ w_a, const float* __restrict__ b_s)
{
    __shared__ float sX[16][64];   // [kk][row]  (x tile, transposed)
    __shared__ float sW[16][64];   // [kk][col]

    const int z = blockIdx.z;
    const float* __restrict__ w = z ? w_a : u_a;
    float* __restrict__ outp = z ? g_right : g_left;

    const int row0 = blockIdx.y * 64;
    const int col0 = blockIdx.x * 64;
    const int tid = threadIdx.x;
    const int tx = tid & 15, ty = tid >> 4;

    unsigned long long acc[4][2];
#pragma unroll
    for (int i = 0; i < 4; i++) { acc[i][0] = 0ull; acc[i][1] = 0ull; }

    const int lr = tid >> 2;            // 0..63  (x tile row)
    const int lk = (tid & 3) << 2;      // 0,4,8,12
    const int wk = tid >> 4;            // 0..15  (w tile k)
    const int wc = (tid & 15) << 2;     // col offset

    for (int k0 = 0; k0 < H_; k0 += 16) {
        float4 gx = *(const float4*)&x[(row0 + lr) * H_ + k0 + lk];
        float4 gw = *(const float4*)&w[(k0 + wk) * K_ + col0 + wc];
        __syncthreads();
        sX[lk + 0][lr] = gx.x; sX[lk + 1][lr] = gx.y;
        sX[lk + 2][lr] = gx.z; sX[lk + 3][lr] = gx.w;
        *(float4*)&sW[wk][wc] = gw;
        __syncthreads();
#pragma unroll
        for (int kk = 0; kk < 16; kk++) {
            float4 a4 = *(const float4*)&sX[kk][ty * 4];
            float4 b4 = *(const float4*)&sW[kk][tx * 4];
            unsigned long long b01 = pack2(b4.x, b4.y);
            unsigned long long b23 = pack2(b4.z, b4.w);
            unsigned long long a0 = pack2(a4.x, a4.x);
            unsigned long long a1 = pack2(a4.y, a4.y);
            unsigned long long a2 = pack2(a4.z, a4.z);
            unsigned long long a3 = pack2(a4.w, a4.w);
            fma2(acc[0][0], a0, b01); fma2(acc[0][1], a0, b23);
            fma2(acc[1][0], a1, b01); fma2(acc[1][1], a1, b23);
            fma2(acc[2][0], a2, b01); fma2(acc[2][1], a2, b23);
            fma2(acc[3][0], a3, b01); fma2(acc[3][1], a3, b23);
        }
    }

    const int col = col0 + tx * 4;
#pragma unroll
    for (int i = 0; i < 4; i++) {
        float4 o;
        unpack2(acc[i][0], o.x, o.y);
        unpack2(acc[i][1], o.z, o.w);
        if (!z) {
            o.x += b_s[col + 0]; o.y += b_s[col + 1];
            o.z += b_s[col + 2]; o.w += b_s[col + 3];
        }
        *(float4*)&outp[(row0 + ty * 4 + i) * K_ + col] = o;
    }
}

// ---------------- Kernel 2: fused tanh(outer) @ v ----------------
// Block tile = 16 i x 32 j of one batch; thread owns TWO (i,j) pairs:
// (i0+ti, j0+tj) and (i0+ti, j0+tj+16). Per k it loads V once (13 LDS.128
// broadcast) and does 52 FFMA2 -> FMA-pipe bound instead of LSU-bound.
__global__ __launch_bounds__(256) void fused_tanh_gemm_kernel(
    const float* __restrict__ v, float* __restrict__ out)
{
    extern __shared__ float smem2[];
    float* sL = smem2;                  // 16 * LRS
    float* sR = smem2 + 16 * LRS;       // 32 * LRS
    float* sV = smem2 + 48 * LRS;       // K_ * PP

    const int b  = blockIdx.z;
    const int i0 = blockIdx.y * 16;
    const int j0 = blockIdx.x * 32;
    const int tid = threadIdx.x;

    // stage v (zero-pad cols 50,51 so the padded accumulators stay finite)
    for (int idx = tid; idx < K_ * PP; idx += 256) {
        int k = idx / PP;
        int p = idx - k * PP;
        sV[idx] = (p < P_) ? v[k * P_ + p] : 0.0f;
    }
    // stage 16 left rows and 32 right rows (each row = K_ floats, coalesced)
    const float* gl = g_left  + (b * S_ + i0) * K_;
    const float* gr = g_right + (b * S_ + j0) * K_;
#pragma unroll
    for (int r = 0; r < 16; r++)
        sL[r * LRS + tid] = gl[r * K_ + tid];
#pragma unroll
    for (int r = 0; r < 32; r++)
        sR[r * LRS + tid] = gr[r * K_ + tid];
    __syncthreads();

    const int ti = tid >> 4;
    const int tj = tid & 15;
    const float* myL  = sL + ti * LRS;
    const float* myR0 = sR + tj * LRS;
    const float* myR1 = sR + (tj + 16) * LRS;

    unsigned long long accA[26], accB[26];
#pragma unroll
    for (int q = 0; q < 26; q++) { accA[q] = 0ull; accB[q] = 0ull; }

#pragma unroll 2
    for (int k2 = 0; k2 < K_; k2 += 2) {
        float2 l2  = *(const float2*)&myL[k2];
        float2 r2a = *(const float2*)&myR0[k2];
        float2 r2b = *(const float2*)&myR1[k2];
#pragma unroll
        for (int s = 0; s < 2; s++) {
            float lv = s ? l2.y : l2.x;
            float a0 = lv + (s ? r2a.y : r2a.x);
            float a1 = lv + (s ? r2b.y : r2b.x);
            // accurate tanh: 1 - 2/(e^{2a}+1)
            float e0 = __expf(a0 + a0);
            float e1 = __expf(a1 + a1);
            float t0 = 1.0f - __fdividef(2.0f, e0 + 1.0f);
            float t1 = 1.0f - __fdividef(2.0f, e1 + 1.0f);
            unsigned long long t0_2 = pack2(t0, t0);
            unsigned long long t1_2 = pack2(t1, t1);
            const ulonglong2* vp = (const ulonglong2*)(sV + (k2 + s) * PP);
#pragma unroll
            for (int q = 0; q < 13; q++) {
                ulonglong2 vv = vp[q];                 // one broadcast LDS.128
                fma2(accA[2 * q + 0], t0_2, vv.x);     // reused for both j's
                fma2(accA[2 * q + 1], t0_2, vv.y);
                fma2(accB[2 * q + 0], t1_2, vv.x);
                fma2(accB[2 * q + 1], t1_2, vv.y);
            }
        }
    }

    const size_t rowbase = (size_t)((b * S_ + i0 + ti) * S_);
    float* orowA = out + (rowbase + j0 + tj) * P_;
    float* orowB = out + (rowbase + j0 + tj + 16) * P_;
#pragma unroll
    for (int q = 0; q < 25; q++) {   // 50 floats as 25 float2 stores (8B aligned)
        float lo, hi;
        unpack2(accA[q], lo, hi);
        *(float2*)&orowA[2 * q] = make_float2(lo, hi);
        unpack2(accB[q], lo, hi);
        *(float2*)&orowB[2 * q] = make_float2(lo, hi);
    }
}

static const int SMEM2_BYTES = (48 * LRS + K_ * PP) * (int)sizeof(float);  // 102784

extern "C" void kernel_launch(void* const* d_in, const int* in_sizes, int n_in,
                              void* d_out, int out_size) {
    const float* x   = (const float*)d_in[0];
    const float* u_a = (const float*)d_in[1];
    const float* w_a = (const float*)d_in[2];
    const float* b_s = (const float*)d_in[3];
    const float* v   = (const float*)d_in[4];
    float* out = (float*)d_out;

    // Opt in to >48 KB dynamic smem (idempotent; safe under graph capture).
    cudaFuncSetAttribute(fused_tanh_gemm_kernel,
                         cudaFuncAttributeMaxDynamicSharedMemorySize, SMEM2_BYTES);

    dim3 g1(K_ / 64, (B_ * S_) / 64, 2);      // (4, 32, 2)
    gemm_lr_kernel<<<g1, 256>>>(x, u_a, w_a, b_s);

    dim3 g2(S_ / 32, S_ / 16, B_);            // (8, 16, 8)
    fused_tanh_gemm_kernel<<<g2, 256, SMEM2_BYTES>>>(v, out);
}

// round 6
// speedup vs baseline: 1.0255x; 1.0139x over previous
#include <cuda_runtime.h>
#include <cstdint>

#define B_ 8
#define S_ 256
#define H_ 768
#define K_ 256
#define P_ 50
#define PP 52          // padded P (13 float4); split 26+26 across tp
#define LRS 258        // smem row stride: even (8B rows), 258 % 32 == 2 -> conflict-free

// Scratch for the two projection GEMMs (allocation-free rule: device globals)
__device__ __align__(16) float g_left [B_ * S_ * K_];   // left  = x@u_a + b_s
__device__ __align__(16) float g_right[B_ * S_ * K_];   // right = x@w_a

// ---------------- packed f32x2 helpers (Blackwell FFMA2 path) ----------------
__device__ __forceinline__ unsigned long long pack2(float a, float b) {
    unsigned long long r;
    asm("mov.b64 %0, {%1, %2};" : "=l"(r)
        : "r"(__float_as_uint(a)), "r"(__float_as_uint(b)));
    return r;
}
__device__ __forceinline__ void fma2(unsigned long long& d,
                                     unsigned long long a, unsigned long long b) {
    asm("fma.rn.f32x2 %0, %1, %2, %0;" : "+l"(d) : "l"(a), "l"(b));
}
__device__ __forceinline__ void unpack2(unsigned long long p, float& lo, float& hi) {
    unsigned int l, h;
    asm("mov.b64 {%0, %1}, %2;" : "=r"(l), "=r"(h) : "l"(p));
    lo = __uint_as_float(l);
    hi = __uint_as_float(h);
}

// ---------------- Kernel 1: left/right projections (fused bias) ----------------
__global__ __launch_bounds__(256) void gemm_lr_kernel(
    const float* __restrict__ x, const float* __restrict__ u_a,
    const float* __restrict__ w_a, const float* __restrict__ b_s)
{
    __shared__ float sX[16][64];   // [kk][row]  (x tile, transposed)
    __shared__ float sW[16][64];   // [kk][col]

    const int z = blockIdx.z;
    const float* __restrict__ w = z ? w_a : u_a;
    float* __restrict__ outp = z ? g_right : g_left;

    const int row0 = blockIdx.y * 64;
    const int col0 = blockIdx.x * 64;
    const int tid = threadIdx.x;
    const int tx = tid & 15, ty = tid >> 4;

    unsigned long long acc[4][2];
#pragma unroll
    for (int i = 0; i < 4; i++) { acc[i][0] = 0ull; acc[i][1] = 0ull; }

    const int lr = tid >> 2;            // 0..63  (x tile row)
    const int lk = (tid & 3) << 2;      // 0,4,8,12
    const int wk = tid >> 4;            // 0..15  (w tile k)
    const int wc = (tid & 15) << 2;     // col offset

    for (int k0 = 0; k0 < H_; k0 += 16) {
        float4 gx = *(const float4*)&x[(row0 + lr) * H_ + k0 + lk];
        float4 gw = *(const float4*)&w[(k0 + wk) * K_ + col0 + wc];
        __syncthreads();
        sX[lk + 0][lr] = gx.x; sX[lk + 1][lr] = gx.y;
        sX[lk + 2][lr] = gx.z; sX[lk + 3][lr] = gx.w;
        *(float4*)&sW[wk][wc] = gw;
        __syncthreads();
#pragma unroll
        for (int kk = 0; kk < 16; kk++) {
            float4 a4 = *(const float4*)&sX[kk][ty * 4];
            float4 b4 = *(const float4*)&sW[kk][tx * 4];
            unsigned long long b01 = pack2(b4.x, b4.y);
            unsigned long long b23 = pack2(b4.z, b4.w);
            unsigned long long a0 = pack2(a4.x, a4.x);
            unsigned long long a1 = pack2(a4.y, a4.y);
            unsigned long long a2 = pack2(a4.z, a4.z);
            unsigned long long a3 = pack2(a4.w, a4.w);
            fma2(acc[0][0], a0, b01); fma2(acc[0][1], a0, b23);
            fma2(acc[1][0], a1, b01); fma2(acc[1][1], a1, b23);
            fma2(acc[2][0], a2, b01); fma2(acc[2][1], a2, b23);
            fma2(acc[3][0], a3, b01); fma2(acc[3][1], a3, b23);
        }
    }

    const int col = col0 + tx * 4;
#pragma unroll
    for (int i = 0; i < 4; i++) {
        float4 o;
        unpack2(acc[i][0], o.x, o.y);
        unpack2(acc[i][1], o.z, o.w);
        if (!z) {
            o.x += b_s[col + 0]; o.y += b_s[col + 1];
            o.z += b_s[col + 2]; o.w += b_s[col + 3];
        }
        *(float4*)&outp[(row0 + ty * 4 + i) * K_ + col] = o;
    }
}

// ---------------- Kernel 2: fused tanh(outer) @ v ----------------
// Block = 512 threads, tile 16 i x 32 j of one batch, P split in two halves.
// Thread (ti, tj, tp): owns (i0+ti, j0+tj) and (i0+ti, j0+tj+16) for P-half tp.
// Per k: 2 tanh (duplicated across tp — cheap), 13 broadcast LDS.64 of V-half,
// 26 FFMA2. 26 u64 accumulators -> ~100 regs -> 16 warps/SM (4/SMSP) so the
// tanh/LDS latency chains are covered (R5 showed 8 warps stall at issue=47%).
__global__ __launch_bounds__(512) void fused_tanh_gemm_kernel(
    const float* __restrict__ v, float* __restrict__ out)
{
    extern __shared__ float smem2[];
    float* sL = smem2;                  // 16 * LRS
    float* sR = smem2 + 16 * LRS;       // 32 * LRS
    float* sV = smem2 + 48 * LRS;       // K_ * PP

    const int b  = blockIdx.z;
    const int i0 = blockIdx.y * 16;
    const int j0 = blockIdx.x * 32;
    const int tid = threadIdx.x;

    // stage v (zero-pad cols 50,51 so padded accumulators stay finite)
    for (int idx = tid; idx < K_ * PP; idx += 512) {
        int k = idx / PP;
        int p = idx - k * PP;
        sV[idx] = (p < P_) ? v[k * P_ + p] : 0.0f;
    }
    // stage 16 left rows and 32 right rows (each row = K_ floats, coalesced)
    const float* gl = g_left  + (b * S_ + i0) * K_;
    const float* gr = g_right + (b * S_ + j0) * K_;
#pragma unroll
    for (int idx = tid; idx < 16 * K_; idx += 512) {
        int r = idx >> 8, c = idx & (K_ - 1);
        sL[r * LRS + c] = gl[r * K_ + c];
    }
#pragma unroll
    for (int idx = tid; idx < 32 * K_; idx += 512) {
        int r = idx >> 8, c = idx & (K_ - 1);
        sR[r * LRS + c] = gr[r * K_ + c];
    }
    __syncthreads();

    const int tj = tid & 15;
    const int ti = (tid >> 4) & 15;
    const int tp = tid >> 8;            // 0 or 1: which P-half
    const int pbase = tp * 26;          // float offset into PP row (8B aligned)

    const float* myL  = sL + ti * LRS;
    const float* myR0 = sR + tj * LRS;
    const float* myR1 = sR + (tj + 16) * LRS;
    const float* vhalf = sV + pbase;

    unsigned long long accA[13], accB[13];
#pragma unroll
    for (int q = 0; q < 13; q++) { accA[q] = 0ull; accB[q] = 0ull; }

#pragma unroll 2
    for (int k2 = 0; k2 < K_; k2 += 2) {
        float2 l2  = *(const float2*)&myL[k2];
        float2 r2a = *(const float2*)&myR0[k2];
        float2 r2b = *(const float2*)&myR1[k2];
#pragma unroll
        for (int s = 0; s < 2; s++) {
            float lv = s ? l2.y : l2.x;
            float a0 = lv + (s ? r2a.y : r2a.x);
            float a1 = lv + (s ? r2b.y : r2b.x);
            // accurate tanh: 1 - 2/(e^{2a}+1)
            float e0 = __expf(a0 + a0);
            float e1 = __expf(a1 + a1);
            float t0 = 1.0f - __fdividef(2.0f, e0 + 1.0f);
            float t1 = 1.0f - __fdividef(2.0f, e1 + 1.0f);
            unsigned long long t0_2 = pack2(t0, t0);
            unsigned long long t1_2 = pack2(t1, t1);
            const unsigned long long* vp =
                (const unsigned long long*)(vhalf + (k2 + s) * PP);
#pragma unroll
            for (int q = 0; q < 13; q++) {
                unsigned long long vv = vp[q];         // broadcast LDS.64
                fma2(accA[q], t0_2, vv);
                fma2(accB[q], t1_2, vv);
            }
        }
    }

    const size_t rowbase = (size_t)((b * S_ + i0 + ti) * S_);
    float* orowA = out + (rowbase + j0 + tj) * P_ + pbase;
    float* orowB = out + (rowbase + j0 + tj + 16) * P_ + pbase;
#pragma unroll
    for (int q = 0; q < 13; q++) {   // tp0: 13 float2 (p0..49 lower half); tp1: 12 (skip pad)
        if (pbase + 2 * q < P_ - 1) {
            float lo, hi;
            unpack2(accA[q], lo, hi);
            *(float2*)&orowA[2 * q] = make_float2(lo, hi);
            unpack2(accB[q], lo, hi);
            *(float2*)&orowB[2 * q] = make_float2(lo, hi);
        }
    }
}

static const int SMEM2_BYTES = (48 * LRS + K_ * PP) * (int)sizeof(float);  // 102784

extern "C" void kernel_launch(void* const* d_in, const int* in_sizes, int n_in,
                              void* d_out, int out_size) {
    const float* x   = (const float*)d_in[0];
    const float* u_a = (const float*)d_in[1];
    const float* w_a = (const float*)d_in[2];
    const float* b_s = (const float*)d_in[3];
    const float* v   = (const float*)d_in[4];
    float* out = (float*)d_out;

    // Opt in to >48 KB dynamic smem (idempotent; safe under graph capture).
    cudaFuncSetAttribute(fused_tanh_gemm_kernel,
                         cudaFuncAttributeMaxDynamicSharedMemorySize, SMEM2_BYTES);

    dim3 g1(K_ / 64, (B_ * S_) / 64, 2);      // (4, 32, 2)
    gemm_lr_kernel<<<g1, 256>>>(x, u_a, w_a, b_s);

    dim3 g2(S_ / 32, S_ / 16, B_);            // (8, 16, 8)
    fused_tanh_gemm_kernel<<<g2, 512, SMEM2_BYTES>>>(v, out);
}

// round 9
// speedup vs baseline: 1.9213x; 1.8736x over previous
#include <cuda_runtime.h>
#include <cuda_bf16.h>
#include <cstdint>

#define B_ 8
#define S_ 256
#define H_ 768
#define K_ 256
#define P_ 50
#define VSTRIDE 132    // V smem row stride in b32: bank = 4n+c -> conflict-free

// Scratch for the two projection GEMMs (allocation-free rule: device globals)
__device__ __align__(16) float g_left [B_ * S_ * K_];   // left  = x@u_a + b_s
__device__ __align__(16) float g_right[B_ * S_ * K_];   // right = x@w_a

// ---------------- packed f32x2 helpers (Blackwell FFMA2 path) ----------------
__device__ __forceinline__ unsigned long long pack2(float a, float b) {
    unsigned long long r;
    asm("mov.b64 %0, {%1, %2};" : "=l"(r)
        : "r"(__float_as_uint(a)), "r"(__float_as_uint(b)));
    return r;
}
__device__ __forceinline__ void fma2(unsigned long long& d,
                                     unsigned long long a, unsigned long long b) {
    asm("fma.rn.f32x2 %0, %1, %2, %0;" : "+l"(d) : "l"(a), "l"(b));
}
__device__ __forceinline__ void unpack2(unsigned long long p, float& lo, float& hi) {
    unsigned int l, h;
    asm("mov.b64 {%0, %1}, %2;" : "=r"(l), "=r"(h) : "l"(p));
    lo = __uint_as_float(l);
    hi = __uint_as_float(h);
}

// ---------------- bf16 split helpers ----------------
// pack two f32 -> bf16x2; first arg lands in the LOW 16 bits
__device__ __forceinline__ uint32_t bf16x2(float lo, float hi) {
    uint32_t r;
    asm("cvt.rn.bf16x2.f32 %0, %1, %2;" : "=r"(r) : "f"(hi), "f"(lo));
    return r;
}
__device__ __forceinline__ float lo16f(uint32_t p) { return __uint_as_float(p << 16); }
__device__ __forceinline__ float hi16f(uint32_t p) { return __uint_as_float(p & 0xffff0000u); }

__device__ __forceinline__ float tanh_acc(float a) {
    float e = __expf(a + a);
    return 1.0f - __fdividef(2.0f, e + 1.0f);
}

// classic warp-level bf16 MMA (sm_80+; works on sm_100 base target)
__device__ __forceinline__ void mma16816(float* d, uint32_t a0, uint32_t a1,
                                         uint32_t a2, uint32_t a3,
                                         uint32_t b0, uint32_t b1) {
    asm volatile(
        "mma.sync.aligned.m16n8k16.row.col.f32.bf16.bf16.f32 "
        "{%0,%1,%2,%3}, {%4,%5,%6,%7}, {%8,%9}, {%0,%1,%2,%3};"
        : "+f"(d[0]), "+f"(d[1]), "+f"(d[2]), "+f"(d[3])
        : "r"(a0), "r"(a1), "r"(a2), "r"(a3), "r"(b0), "r"(b1));
}

// ---------------- Kernel 1: left/right projections (fused bias) ----------------
__global__ __launch_bounds__(256) void gemm_lr_kernel(
    const float* __restrict__ x, const float* __restrict__ u_a,
    const float* __restrict__ w_a, const float* __restrict__ b_s)
{
    __shared__ float sX[16][64];
    __shared__ float sW[16][64];

    const int z = blockIdx.z;
    const float* __restrict__ w = z ? w_a : u_a;
    float* __restrict__ outp = z ? g_right : g_left;

    const int row0 = blockIdx.y * 64;
    const int col0 = blockIdx.x * 64;
    const int tid = threadIdx.x;
    const int tx = tid & 15, ty = tid >> 4;

    unsigned long long acc[4][2];
#pragma unroll
    for (int i = 0; i < 4; i++) { acc[i][0] = 0ull; acc[i][1] = 0ull; }

    const int lr = tid >> 2;
    const int lk = (tid & 3) << 2;
    const int wk = tid >> 4;
    const int wc = (tid & 15) << 2;

    for (int k0 = 0; k0 < H_; k0 += 16) {
        float4 gx = *(const float4*)&x[(row0 + lr) * H_ + k0 + lk];
        float4 gw = *(const float4*)&w[(k0 + wk) * K_ + col0 + wc];
        __syncthreads();
        sX[lk + 0][lr] = gx.x; sX[lk + 1][lr] = gx.y;
        sX[lk + 2][lr] = gx.z; sX[lk + 3][lr] = gx.w;
        *(float4*)&sW[wk][wc] = gw;
        __syncthreads();
#pragma unroll
        for (int kk = 0; kk < 16; kk++) {
            float4 a4 = *(const float4*)&sX[kk][ty * 4];
            float4 b4 = *(const float4*)&sW[kk][tx * 4];
            unsigned long long b01 = pack2(b4.x, b4.y);
            unsigned long long b23 = pack2(b4.z, b4.w);
            unsigned long long a0 = pack2(a4.x, a4.x);
            unsigned long long a1 = pack2(a4.y, a4.y);
            unsigned long long a2 = pack2(a4.z, a4.z);
            unsigned long long a3 = pack2(a4.w, a4.w);
            fma2(acc[0][0], a0, b01); fma2(acc[0][1], a0, b23);
            fma2(acc[1][0], a1, b01); fma2(acc[1][1], a1, b23);
            fma2(acc[2][0], a2, b01); fma2(acc[2][1], a2, b23);
            fma2(acc[3][0], a3, b01); fma2(acc[3][1], a3, b23);
        }
    }

    const int col = col0 + tx * 4;
#pragma unroll
    for (int i = 0; i < 4; i++) {
        float4 o;
        unpack2(acc[i][0], o.x, o.y);
        unpack2(acc[i][1], o.z, o.w);
        if (!z) {
            o.x += b_s[col + 0]; o.y += b_s[col + 1];
            o.z += b_s[col + 2]; o.w += b_s[col + 3];
        }
        *(float4*)&outp[(row0 + ty * 4 + i) * K_ + col] = o;
    }
}

// ---------------- Kernel 2: register-direct tanh -> mma.sync bf16-split ----------------
// CTA = one (b, i); 512 threads = 16 warps, warp w owns j-rows [w*16, w*16+16).
// Each thread computes its m16n8k16 A-fragment elements directly:
//   lane -> group = lane>>2 (row j = w*16+group / +8), c = lane&3 (k = 2c,2c+1 / +8,+9)
// A = tanh(l_i[k] + r_j[k]) split into bf16 hi + lo (registers only, no smem A).
// B = v^T (n-major, k-pairs packed bf16x2, hi/lo) staged once in smem.
// D accumulated over 16 k-chunks x 7 n-tiles x 3 passes (hi*hi + lo*hi + hi*lo).
#define SVHI_OFF 1024
#define SVLO_OFF (1024 + 56 * VSTRIDE * 4)
#define SMEM2_BYTES (1024 + 2 * 56 * VSTRIDE * 4)   // 60160

__global__ __launch_bounds__(512) void fused_tanh_mma_kernel(
    const float* __restrict__ v, float* __restrict__ out)
{
    extern __shared__ char smem[];
    float*    sL   = (float*)smem;                  // 256 f32 (l_i row, bias folded)
    uint32_t* sVhi = (uint32_t*)(smem + SVHI_OFF);  // [56][VSTRIDE] b32 (k-pairs)
    uint32_t* sVlo = (uint32_t*)(smem + SVLO_OFF);

    const int tid = threadIdx.x;
    const int i = blockIdx.x;
    const int b = blockIdx.y;

    for (int k = tid; k < K_; k += 512)
        sL[k] = g_left[(size_t)(b * S_ + i) * K_ + k];

    // stage V^T hi/lo: row n (0..55, zero-padded >=50), col kk packs (k=2kk, 2kk+1)
    for (int idx = tid; idx < 56 * 128; idx += 512) {
        int n = idx >> 7;
        int kk = idx & 127;
        int k = kk << 1;
        float v0 = 0.0f, v1 = 0.0f;
        if (n < P_) { v0 = v[k * P_ + n]; v1 = v[(k + 1) * P_ + n]; }
        uint32_t hp = bf16x2(v0, v1);
        uint32_t lp = bf16x2(v0 - lo16f(hp), v1 - hi16f(hp));
        sVhi[n * VSTRIDE + kk] = hp;
        sVlo[n * VSTRIDE + kk] = lp;
    }
    __syncthreads();

    const int w = tid >> 5, lane = tid & 31;
    const int group = lane >> 2, c = lane & 3;
    const int j0 = w * 16 + group;          // A rows this thread covers
    const int j1 = j0 + 8;
    const float* rp0 = g_right + (size_t)(b * S_ + j0) * K_ + 2 * c;
    const float* rp1 = g_right + (size_t)(b * S_ + j1) * K_ + 2 * c;

    float d[7][4];
#pragma unroll
    for (int nt = 0; nt < 7; nt++)
#pragma unroll
        for (int q = 0; q < 4; q++) d[nt][q] = 0.0f;

    // prefetch chunk 0 r-values (L2-resident; coalesced 32B per lane group)
    float2 rA0 = *(const float2*)rp0;
    float2 rA2 = *(const float2*)(rp0 + 8);
    float2 rB0 = *(const float2*)rp1;
    float2 rB2 = *(const float2*)(rp1 + 8);

#pragma unroll
    for (int ch = 0; ch < 16; ch++) {
        const int k0 = ch * 16;
        float2 l0 = *(const float2*)&sL[k0 + 2 * c];
        float2 l2 = *(const float2*)&sL[k0 + 2 * c + 8];

        float ta0x = tanh_acc(l0.x + rA0.x), ta0y = tanh_acc(l0.y + rA0.y);
        float ta1x = tanh_acc(l0.x + rB0.x), ta1y = tanh_acc(l0.y + rB0.y);
        float ta2x = tanh_acc(l2.x + rA2.x), ta2y = tanh_acc(l2.y + rA2.y);
        float ta3x = tanh_acc(l2.x + rB2.x), ta3y = tanh_acc(l2.y + rB2.y);

        // prefetch next chunk's r while tanh/mma proceed
        if (ch < 15) {
            const float* q0 = rp0 + (ch + 1) * 16;
            const float* q1 = rp1 + (ch + 1) * 16;
            rA0 = *(const float2*)q0; rA2 = *(const float2*)(q0 + 8);
            rB0 = *(const float2*)q1; rB2 = *(const float2*)(q1 + 8);
        }

        uint32_t a0h = bf16x2(ta0x, ta0y);
        uint32_t a1h = bf16x2(ta1x, ta1y);
        uint32_t a2h = bf16x2(ta2x, ta2y);
        uint32_t a3h = bf16x2(ta3x, ta3y);
        uint32_t a0l = bf16x2(ta0x - lo16f(a0h), ta0y - hi16f(a0h));
        uint32_t a1l = bf16x2(ta1x - lo16f(a1h), ta1y - hi16f(a1h));
        uint32_t a2l = bf16x2(ta2x - lo16f(a2h), ta2y - hi16f(a2h));
        uint32_t a3l = bf16x2(ta3x - lo16f(a3h), ta3y - hi16f(a3h));

        const uint32_t* ph = sVhi + (ch << 3) + c;   // + n*VSTRIDE
        const uint32_t* pl = sVlo + (ch << 3) + c;
#pragma unroll
        for (int nt = 0; nt < 7; nt++) {
            const int off = (nt * 8 + group) * VSTRIDE;
            uint32_t b0h = ph[off], b1h = ph[off + 4];
            uint32_t b0l = pl[off], b1l = pl[off + 4];
            mma16816(d[nt], a0h, a1h, a2h, a3h, b0h, b1h);   // hi*hi
            mma16816(d[nt], a0l, a1l, a2l, a3l, b0h, b1h);   // lo*hi
            mma16816(d[nt], a0h, a1h, a2h, a3h, b0l, b1l);   // hi*lo
        }
    }

    // epilogue: d[nt] rows (j0, j1), cols p = nt*8 + 2c (+1); only p<50
    float* obase = out + (size_t)(b * S_ + i) * S_ * P_;
#pragma unroll
    for (int nt = 0; nt < 7; nt++) {
        const int p0 = nt * 8 + 2 * c;
        if (p0 < P_) {   // p0 even, p0<=48 -> p0+1<=49 safe
            *(float2*)(obase + (size_t)j0 * P_ + p0) = make_float2(d[nt][0], d[nt][1]);
            *(float2*)(obase + (size_t)j1 * P_ + p0) = make_float2(d[nt][2], d[nt][3]);
        }
    }
}

extern "C" void kernel_launch(void* const* d_in, const int* in_sizes, int n_in,
                              void* d_out, int out_size) {
    const float* x   = (const float*)d_in[0];
    const float* u_a = (const float*)d_in[1];
    const float* w_a = (const float*)d_in[2];
    const float* b_s = (const float*)d_in[3];
    const float* v   = (const float*)d_in[4];
    float* out = (float*)d_out;

    cudaFuncSetAttribute(fused_tanh_mma_kernel,
                         cudaFuncAttributeMaxDynamicSharedMemorySize, SMEM2_BYTES);

    dim3 g1(K_ / 64, (B_ * S_) / 64, 2);      // (4, 32, 2)
    gemm_lr_kernel<<<g1, 256>>>(x, u_a, w_a, b_s);

    dim3 g2(S_, B_);                           // (i, b) = 2048 CTAs
    fused_tanh_mma_kernel<<<g2, 512, SMEM2_BYTES>>>(v, out);
}

// round 10
// speedup vs baseline: 2.0365x; 1.0600x over previous
#include <cuda_runtime.h>
#include <cuda_bf16.h>
#include <cstdint>

#define B_ 8
#define S_ 256
#define H_ 768
#define K_ 256
#define P_ 50
#define VSTRIDE 132    // V smem row stride in b32: bank = 4*group+c -> conflict-free

// Scratch for the two projection GEMMs (allocation-free rule: device globals)
__device__ __align__(16) float g_left [B_ * S_ * K_];   // left  = x@u_a + b_s
__device__ __align__(16) float g_right[B_ * S_ * K_];   // right = x@w_a

// ---------------- packed f32x2 helpers (Blackwell FFMA2 path) ----------------
__device__ __forceinline__ unsigned long long pack2(float a, float b) {
    unsigned long long r;
    asm("mov.b64 %0, {%1, %2};" : "=l"(r)
        : "r"(__float_as_uint(a)), "r"(__float_as_uint(b)));
    return r;
}
__device__ __forceinline__ void fma2(unsigned long long& d,
                                     unsigned long long a, unsigned long long b) {
    asm("fma.rn.f32x2 %0, %1, %2, %0;" : "+l"(d) : "l"(a), "l"(b));
}
__device__ __forceinline__ void unpack2(unsigned long long p, float& lo, float& hi) {
    unsigned int l, h;
    asm("mov.b64 {%0, %1}, %2;" : "=r"(l), "=r"(h) : "l"(p));
    lo = __uint_as_float(l);
    hi = __uint_as_float(h);
}

// ---------------- bf16 split helpers ----------------
// pack two f32 -> bf16x2; first arg lands in the LOW 16 bits
__device__ __forceinline__ uint32_t bf16x2(float lo, float hi) {
    uint32_t r;
    asm("cvt.rn.bf16x2.f32 %0, %1, %2;" : "=r"(r) : "f"(hi), "f"(lo));
    return r;
}
__device__ __forceinline__ float lo16f(uint32_t p) { return __uint_as_float(p << 16); }
__device__ __forceinline__ float hi16f(uint32_t p) { return __uint_as_float(p & 0xffff0000u); }

__device__ __forceinline__ float tanh_acc(float a) {
    float e = __expf(a + a);
    return 1.0f - __fdividef(2.0f, e + 1.0f);
}

// classic warp-level bf16 MMA (sm_80+; works on sm_100 base target)
__device__ __forceinline__ void mma16816(float* d, uint32_t a0, uint32_t a1,
                                         uint32_t a2, uint32_t a3,
                                         uint32_t b0, uint32_t b1) {
    asm volatile(
        "mma.sync.aligned.m16n8k16.row.col.f32.bf16.bf16.f32 "
        "{%0,%1,%2,%3}, {%4,%5,%6,%7}, {%8,%9}, {%0,%1,%2,%3};"
        : "+f"(d[0]), "+f"(d[1]), "+f"(d[2]), "+f"(d[3])
        : "r"(a0), "r"(a1), "r"(a2), "r"(a3), "r"(b0), "r"(b1));
}

// ---------------- Kernel 1: left/right projections (fused bias) ----------------
__global__ __launch_bounds__(256) void gemm_lr_kernel(
    const float* __restrict__ x, const float* __restrict__ u_a,
    const float* __restrict__ w_a, const float* __restrict__ b_s)
{
    __shared__ float sX[16][64];
    __shared__ float sW[16][64];

    const int z = blockIdx.z;
    const float* __restrict__ w = z ? w_a : u_a;
    float* __restrict__ outp = z ? g_right : g_left;

    const int row0 = blockIdx.y * 64;
    const int col0 = blockIdx.x * 64;
    const int tid = threadIdx.x;
    const int tx = tid & 15, ty = tid >> 4;

    unsigned long long acc[4][2];
#pragma unroll
    for (int i = 0; i < 4; i++) { acc[i][0] = 0ull; acc[i][1] = 0ull; }

    const int lr = tid >> 2;
    const int lk = (tid & 3) << 2;
    const int wk = tid >> 4;
    const int wc = (tid & 15) << 2;

    for (int k0 = 0; k0 < H_; k0 += 16) {
        float4 gx = *(const float4*)&x[(row0 + lr) * H_ + k0 + lk];
        float4 gw = *(const float4*)&w[(k0 + wk) * K_ + col0 + wc];
        __syncthreads();
        sX[lk + 0][lr] = gx.x; sX[lk + 1][lr] = gx.y;
        sX[lk + 2][lr] = gx.z; sX[lk + 3][lr] = gx.w;
        *(float4*)&sW[wk][wc] = gw;
        __syncthreads();
#pragma unroll
        for (int kk = 0; kk < 16; kk++) {
            float4 a4 = *(const float4*)&sX[kk][ty * 4];
            float4 b4 = *(const float4*)&sW[kk][tx * 4];
            unsigned long long b01 = pack2(b4.x, b4.y);
            unsigned long long b23 = pack2(b4.z, b4.w);
            unsigned long long a0 = pack2(a4.x, a4.x);
            unsigned long long a1 = pack2(a4.y, a4.y);
            unsigned long long a2 = pack2(a4.z, a4.z);
            unsigned long long a3 = pack2(a4.w, a4.w);
            fma2(acc[0][0], a0, b01); fma2(acc[0][1], a0, b23);
            fma2(acc[1][0], a1, b01); fma2(acc[1][1], a1, b23);
            fma2(acc[2][0], a2, b01); fma2(acc[2][1], a2, b23);
            fma2(acc[3][0], a3, b01); fma2(acc[3][1], a3, b23);
        }
    }

    const int col = col0 + tx * 4;
#pragma unroll
    for (int i = 0; i < 4; i++) {
        float4 o;
        unpack2(acc[i][0], o.x, o.y);
        unpack2(acc[i][1], o.z, o.w);
        if (!z) {
            o.x += b_s[col + 0]; o.y += b_s[col + 1];
            o.z += b_s[col + 2]; o.w += b_s[col + 3];
        }
        *(float4*)&outp[(row0 + ty * 4 + i) * K_ + col] = o;
    }
}

// ---------------- Kernel 2: register-direct tanh -> mma.sync bf16-split, m32/warp ----
// CTA = 512 threads = 16 warps, covers TWO i-rows x 256 j.
// Warp w: i = i0 + (w>>3); j-range = (w&7)*32 .. +32 (two m16 A-fragment sets).
// Per chunk: B fragments loaded ONCE (28 LDS.32) and reused by 42 HMMA
// (2 m-sets x 7 nt x 3 passes) -> halves R9's L1 traffic per MMA.
#define SVHI_OFF 2048
#define SVLO_OFF (SVHI_OFF + 56 * VSTRIDE * 4)
#define SMEM2_BYTES (SVHI_OFF + 2 * 56 * VSTRIDE * 4)   // 61184

__global__ __launch_bounds__(512) void fused_tanh_mma_kernel(
    const float* __restrict__ v, float* __restrict__ out)
{
    extern __shared__ char smem[];
    float*    sL   = (float*)smem;                  // 2 rows x 256 f32 (bias folded)
    uint32_t* sVhi = (uint32_t*)(smem + SVHI_OFF);  // [56][VSTRIDE] b32 (k-pairs)
    uint32_t* sVlo = (uint32_t*)(smem + SVLO_OFF);

    const int tid = threadIdx.x;
    const int i0 = blockIdx.x * 2;
    const int b  = blockIdx.y;

    // stage two l rows
    sL[tid] = g_left[(size_t)(b * S_ + i0 + (tid >> 8)) * K_ + (tid & 255)];

    // stage V^T hi/lo: row n (0..55, zero-padded >=50), col kk packs (k=2kk, 2kk+1)
    for (int idx = tid; idx < 56 * 128; idx += 512) {
        int n = idx >> 7;
        int kk = idx & 127;
        int k = kk << 1;
        float v0 = 0.0f, v1 = 0.0f;
        if (n < P_) { v0 = v[k * P_ + n]; v1 = v[(k + 1) * P_ + n]; }
        uint32_t hp = bf16x2(v0, v1);
        uint32_t lp = bf16x2(v0 - lo16f(hp), v1 - hi16f(hp));
        sVhi[n * VSTRIDE + kk] = hp;
        sVlo[n * VSTRIDE + kk] = lp;
    }
    __syncthreads();

    const int w = tid >> 5, lane = tid & 31;
    const int group = lane >> 2, c = lane & 3;
    const int iw = w >> 3;                  // which of the 2 i-rows
    const int jb = (w & 7) * 32;            // warp's j base (32 rows)
    const float* lrow = sL + iw * 256;

    // 4 A rows per thread: j = jb+group, +8, +16, +24
    const float* rp[4];
#pragma unroll
    for (int s = 0; s < 4; s++)
        rp[s] = g_right + (size_t)(b * S_ + jb + group + 8 * s) * K_ + 2 * c;

    float d0[7][4], d1[7][4];
#pragma unroll
    for (int nt = 0; nt < 7; nt++)
#pragma unroll
        for (int q = 0; q < 4; q++) { d0[nt][q] = 0.0f; d1[nt][q] = 0.0f; }

    // prefetch chunk 0 r-values (L2-resident; coalesced)
    float2 rlo[4], rhi[4];
#pragma unroll
    for (int s = 0; s < 4; s++) {
        rlo[s] = *(const float2*)rp[s];
        rhi[s] = *(const float2*)(rp[s] + 8);
    }

#pragma unroll
    for (int ch = 0; ch < 16; ch++) {
        const int k0 = ch * 16;
        float2 l0 = *(const float2*)&lrow[k0 + 2 * c];
        float2 l2 = *(const float2*)&lrow[k0 + 2 * c + 8];

        // 16 tanh: 4 rows x (k=2c, 2c+1, 2c+8, 2c+9)
        float tl[4][2], th[4][2];
#pragma unroll
        for (int s = 0; s < 4; s++) {
            tl[s][0] = tanh_acc(l0.x + rlo[s].x);
            tl[s][1] = tanh_acc(l0.y + rlo[s].y);
            th[s][0] = tanh_acc(l2.x + rhi[s].x);
            th[s][1] = tanh_acc(l2.y + rhi[s].y);
        }

        // prefetch next chunk's r while tanh/mma proceed
        if (ch < 15) {
#pragma unroll
            for (int s = 0; s < 4; s++) {
                rlo[s] = *(const float2*)(rp[s] + (ch + 1) * 16);
                rhi[s] = *(const float2*)(rp[s] + (ch + 1) * 16 + 8);
            }
        }

        // pack A fragments: set0 = rows (group, group+8), set1 = (group+16, +24)
        uint32_t aH[8], aL[8];
#pragma unroll
        for (int s = 0; s < 2; s++) {       // s: fragment set
            int ra = 2 * s, rb = 2 * s + 1;
            aH[4*s+0] = bf16x2(tl[ra][0], tl[ra][1]);
            aH[4*s+1] = bf16x2(tl[rb][0], tl[rb][1]);
            aH[4*s+2] = bf16x2(th[ra][0], th[ra][1]);
            aH[4*s+3] = bf16x2(th[rb][0], th[rb][1]);
            aL[4*s+0] = bf16x2(tl[ra][0] - lo16f(aH[4*s+0]), tl[ra][1] - hi16f(aH[4*s+0]));
            aL[4*s+1] = bf16x2(tl[rb][0] - lo16f(aH[4*s+1]), tl[rb][1] - hi16f(aH[4*s+1]));
            aL[4*s+2] = bf16x2(th[ra][0] - lo16f(aH[4*s+2]), th[ra][1] - hi16f(aH[4*s+2]));
            aL[4*s+3] = bf16x2(th[rb][0] - lo16f(aH[4*s+3]), th[rb][1] - hi16f(aH[4*s+3]));
        }

        const uint32_t* ph = sVhi + (ch << 3) + c;   // + n*VSTRIDE
        const uint32_t* pl = sVlo + (ch << 3) + c;
#pragma unroll
        for (int nt = 0; nt < 7; nt++) {
            const int off = (nt * 8 + group) * VSTRIDE;
            uint32_t b0h = ph[off], b1h = ph[off + 4];
            uint32_t b0l = pl[off], b1l = pl[off + 4];
            // set 0 (rows jb+group, jb+group+8)
            mma16816(d0[nt], aH[0], aH[1], aH[2], aH[3], b0h, b1h);   // hi*hi
            mma16816(d0[nt], aL[0], aL[1], aL[2], aL[3], b0h, b1h);   // lo*hi
            mma16816(d0[nt], aH[0], aH[1], aH[2], aH[3], b0l, b1l);   // hi*lo
            // set 1 (rows jb+group+16, +24)
            mma16816(d1[nt], aH[4], aH[5], aH[6], aH[7], b0h, b1h);
            mma16816(d1[nt], aL[4], aL[5], aL[6], aL[7], b0h, b1h);
            mma16816(d1[nt], aH[4], aH[5], aH[6], aH[7], b0l, b1l);
        }
    }

    // epilogue: rows jb+group (+8, +16, +24), cols p = nt*8 + 2c (+1); only p<50
    float* obase = out + (size_t)(b * S_ + i0 + iw) * S_ * P_ + (size_t)(jb + group) * P_;
#pragma unroll
    for (int nt = 0; nt < 7; nt++) {
        const int p0 = nt * 8 + 2 * c;
        if (p0 < P_) {   // p0 even, p0<=48 -> p0+1<=49 safe
            *(float2*)(obase + 0 * 8 * P_ + p0) = make_float2(d0[nt][0], d0[nt][1]);
            *(float2*)(obase + 1 * 8 * P_ + p0) = make_float2(d0[nt][2], d0[nt][3]);
            *(float2*)(obase + 2 * 8 * P_ + p0) = make_float2(d1[nt][0], d1[nt][1]);
            *(float2*)(obase + 3 * 8 * P_ + p0) = make_float2(d1[nt][2], d1[nt][3]);
        }
    }
}

extern "C" void kernel_launch(void* const* d_in, const int* in_sizes, int n_in,
                              void* d_out, int out_size) {
    const float* x   = (const float*)d_in[0];
    const float* u_a = (const float*)d_in[1];
    const float* w_a = (const float*)d_in[2];
    const float* b_s = (const float*)d_in[3];
    const float* v   = (const float*)d_in[4];
    float* out = (float*)d_out;

    cudaFuncSetAttribute(fused_tanh_mma_kernel,
                         cudaFuncAttributeMaxDynamicSharedMemorySize, SMEM2_BYTES);

    dim3 g1(K_ / 64, (B_ * S_) / 64, 2);      // (4, 32, 2)
    gemm_lr_kernel<<<g1, 256>>>(x, u_a, w_a, b_s);

    dim3 g2(S_ / 2, B_);                       // 1024 CTAs (2 i-rows each)
    fused_tanh_mma_kernel<<<g2, 512, SMEM2_BYTES>>>(v, out);
}